// round 1
// baseline (speedup 1.0000x reference)
#include <cuda_runtime.h>
#include <math.h>

#define NCAP 64          // N capsules
#define DDIM 64          // D
#define ROWS 65          // padded smem row stride (floats)
#define TPB  128

__global__ __launch_bounds__(TPB) void routing_kernel(
    const float* __restrict__ x, float* __restrict__ out, int B)
{
    __shared__ float xs[NCAP * ROWS];   // padded tile
    __shared__ float bb[NCAP];          // logits
    __shared__ float cs[NCAP];          // softmax coupling
    __shared__ float vs[DDIM];          // squashed output
    __shared__ float red[64];           // reduction scratch
    __shared__ float scal[2];           // broadcast scalars

    const int bid = blockIdx.x;
    if (bid >= B) return;
    const int tid = threadIdx.x;

    // ---- load 64x64 tile (4096 floats) via float4, store padded ----
    const float4* __restrict__ x4 = (const float4*)(x + (size_t)bid * NCAP * DDIM);
#pragma unroll
    for (int i = 0; i < 8; i++) {
        int idx = tid + i * TPB;          // float4 index 0..1023
        float4 v = x4[idx];
        int row  = idx >> 4;              // 16 float4 per row
        int col  = (idx & 15) << 2;
        float* dst = &xs[row * ROWS + col];
        dst[0] = v.x; dst[1] = v.y; dst[2] = v.z; dst[3] = v.w;
    }
    if (tid < NCAP) bb[tid] = 0.0f;
    __syncthreads();

    float s_d = 0.0f;                     // this thread's s[d] (tid<64)
    float out_d = 0.0f;

#pragma unroll
    for (int it = 0; it < 3; it++) {
        // ---- softmax over bb -> cs ----
        float bn = (tid < NCAP) ? bb[tid] : 0.0f;
        if (tid < 64) red[tid] = bn;
        __syncthreads();
        if (tid < 32) {
            float m = fmaxf(red[tid], red[tid + 32]);
#pragma unroll
            for (int off = 16; off > 0; off >>= 1)
                m = fmaxf(m, __shfl_xor_sync(0xffffffffu, m, off));
            if (tid == 0) scal[0] = m;
        }
        __syncthreads();
        float e = (tid < NCAP) ? __expf(bn - scal[0]) : 0.0f;
        if (tid < 64) red[tid] = e;
        __syncthreads();
        if (tid < 32) {
            float sum = red[tid] + red[tid + 32];
#pragma unroll
            for (int off = 16; off > 0; off >>= 1)
                sum += __shfl_xor_sync(0xffffffffu, sum, off);
            if (tid == 0) scal[1] = sum;
        }
        __syncthreads();
        if (tid < NCAP) cs[tid] = e / scal[1];
        __syncthreads();

        // ---- s[d] = sum_n c[n] * x[n][d]  (thread d, stride-1 smem) ----
        if (tid < DDIM) {
            s_d = 0.0f;
#pragma unroll 8
            for (int n = 0; n < NCAP; n++)
                s_d = fmaf(cs[n], xs[n * ROWS + tid], s_d);
            red[tid] = s_d * s_d;
        }
        __syncthreads();
        if (tid < 32) {
            float sum = red[tid] + red[tid + 32];
#pragma unroll
            for (int off = 16; off > 0; off >>= 1)
                sum += __shfl_xor_sync(0xffffffffu, sum, off);
            if (tid == 0) scal[0] = sum;
        }
        __syncthreads();

        // ---- squash: v = n2/(1+n2)/(nrm+eps) * s ----
        if (tid < DDIM) {
            float n2  = scal[0];
            float nrm = sqrtf(n2);
            float scale = n2 / (1.0f + n2) / (nrm + 1e-8f);
            out_d = scale * s_d;
            vs[tid] = out_d;
        }
        __syncthreads();

        // ---- agreement: b[n] += dot(x[n], v)  (thread n, stride-65 smem) ----
        if (it < 2) {
            if (tid < NCAP) {
                float a = 0.0f;
#pragma unroll 8
                for (int d = 0; d < DDIM; d++)
                    a = fmaf(xs[tid * ROWS + d], vs[d], a);
                bb[tid] += a;
            }
            __syncthreads();
        }
    }

    // ---- write v ----
    if (tid < DDIM) out[(size_t)bid * DDIM + tid] = out_d;
}

extern "C" void kernel_launch(void* const* d_in, const int* in_sizes, int n_in,
                              void* d_out, int out_size)
{
    const float* x = (const float*)d_in[0];
    float* out = (float*)d_out;
    int B = in_sizes[0] / (NCAP * DDIM);
    routing_kernel<<<B, TPB>>>(x, out, B);
}